// round 12
// baseline (speedup 1.0000x reference)
#include <cuda_runtime.h>
#include <cuda_fp16.h>
#include <cstdint>

#define D_IN 64
#define D_E 64
#define D_OUT 128
#define D_APPLY_IN 192
#define MAX_NODES 50000
#define MAX_EDGES 800000

__device__ float g_hneigh[MAX_NODES * D_OUT];
// packed fp16 split rows: per row 128B hi + 128B lo (64 elems each)
__device__ __align__(16) unsigned char g_nconv[(size_t)MAX_NODES * 256];
__device__ __align__(16) unsigned char g_econv[(size_t)MAX_EDGES * 256];

// ============================ helpers ============================
__device__ __forceinline__ void ffma2(unsigned long long& acc,
                                      unsigned long long a, unsigned long long b) {
    asm("fma.rn.f32x2 %0, %1, %2, %0;" : "+l"(acc) : "l"(a), "l"(b));
}
__device__ __forceinline__ float2 unpack2(unsigned long long v) {
    float2 f;
    asm("mov.b64 {%0, %1}, %2;" : "=f"(f.x), "=f"(f.y) : "l"(v));
    return f;
}
__device__ __forceinline__ void red_add_v4(float* p, float a, float b, float c, float d) {
    asm volatile("red.global.add.v4.f32 [%0], {%1, %2, %3, %4};"
                 :: "l"(p), "f"(a), "f"(b), "f"(c), "f"(d) : "memory");
}
__device__ __forceinline__ uint32_t smem_u32(const void* p) {
    uint32_t a;
    asm("{ .reg .u64 t; cvta.to.shared.u64 t, %1; cvt.u32.u64 %0, t; }" : "=r"(a) : "l"(p));
    return a;
}
__device__ __forceinline__ void ldsm4(uint32_t* r, uint32_t addr) {
    asm volatile("ldmatrix.sync.aligned.m8n8.x4.shared.b16 {%0,%1,%2,%3}, [%4];"
                 : "=r"(r[0]), "=r"(r[1]), "=r"(r[2]), "=r"(r[3]) : "r"(addr));
}
__device__ __forceinline__ void mma_f16(float* c, const uint32_t* a, uint32_t b0, uint32_t b1) {
    asm volatile("mma.sync.aligned.m16n8k16.row.col.f32.f16.f16.f32 "
                 "{%0,%1,%2,%3}, {%4,%5,%6,%7}, {%8,%9}, {%0,%1,%2,%3};"
                 : "+f"(c[0]), "+f"(c[1]), "+f"(c[2]), "+f"(c[3])
                 : "r"(a[0]), "r"(a[1]), "r"(a[2]), "r"(a[3]), "r"(b0), "r"(b1));
}
__device__ __forceinline__ void cpa16(uint32_t dst, const void* src) {
    asm volatile("cp.async.cg.shared.global [%0], [%1], 16;" :: "r"(dst), "l"(src));
}
#define CP_COMMIT() asm volatile("cp.async.commit_group;" ::: "memory")
#define CP_WAIT0()  asm volatile("cp.async.wait_group 0;" ::: "memory")
__device__ __forceinline__ void sts_zero16(uint32_t dst) {
    asm volatile("st.shared.v4.b32 [%0], {%1,%1,%1,%1};" :: "r"(dst), "r"(0u));
}

__global__ void zero_hneigh_kernel(int n4) {
    int i = blockIdx.x * blockDim.x + threadIdx.x;
    if (i < n4)
        reinterpret_cast<float4*>(g_hneigh)[i] = make_float4(0.f, 0.f, 0.f, 0.f);
}

// ---------- prepass: fp32 rows -> packed fp16 hi/lo rows (256B/row) ----------
__global__ void conv_split_kernel(const float4* __restrict__ in,
                                  unsigned char* __restrict__ out, int nchunks) {
    int i = blockIdx.x * blockDim.x + threadIdx.x;
    if (i >= nchunks) return;
    int row = i >> 4, q = i & 15;
    float4 v = in[i];
    __half2 h01 = __floats2half2_rn(v.x, v.y);
    __half2 h23 = __floats2half2_rn(v.z, v.w);
    float rx = v.x - __half2float(__low2half(h01));
    float ry = v.y - __half2float(__high2half(h01));
    float rz = v.z - __half2float(__low2half(h23));
    float rw = v.w - __half2float(__high2half(h23));
    __half2 l01 = __floats2half2_rn(rx, ry);
    __half2 l23 = __floats2half2_rn(rz, rw);
    unsigned char* o = out + (size_t)row * 256;
    *reinterpret_cast<__half2*>(o + q * 8)           = h01;
    *reinterpret_cast<__half2*>(o + q * 8 + 4)       = h23;
    *reinterpret_cast<__half2*>(o + 128 + q * 8)     = l01;
    *reinterpret_cast<__half2*>(o + 128 + q * 8 + 4) = l23;
}

// =====================================================================
// Edge kernel v10: R9 shell (2 CTAs/SM x 256 thr, 64-edge tiles),
// fp16 hi/lo K-concat GEMM with SINGLE W copy + B-fragment reuse:
// per kc8: load B once, apply to A(kc8) and A(kc8+8). LDSM -25%.
// smem: W 32KB + X 32KB + bias = 66KB.
// =====================================================================
#define SM_W    0u
#define SM_X    32768u
#define SM_BIAS 65536u
#define SM_EDGE_BYTES 66048u

// X tile: 512B rows (K=256), 16B-chunk XOR swizzle
__device__ __forceinline__ uint32_t toffX(int row, int kchunk) {
    return ((uint32_t)row << 9) + ((uint32_t)(kchunk ^ (row & 7)) << 4);
}
// W tile: 256B rows (K=128), 16B-chunk XOR swizzle
__device__ __forceinline__ uint32_t toffW(int row, int kchunk) {
    return ((uint32_t)row << 8) + ((uint32_t)(kchunk ^ (row & 7)) << 4);
}

__global__ __launch_bounds__(256, 2)
void edge_msg_kernel(const float* __restrict__ Wmsg,
                     const float* __restrict__ bmsg,
                     const int* __restrict__ src,
                     const int* __restrict__ dst,
                     int E)
{
    extern __shared__ char smem[];
    const uint32_t sb = smem_u32(smem);
    const int tid  = threadIdx.x;
    const int lane = tid & 31;
    const int wid  = tid >> 5;

    // ---- W to smem: W[n][k] = fp16(Wmsg[k][n]), k = 0..127, swizzled ----
    for (int i = tid; i < 128 * 128; i += 256) {
        int n = i >> 7, k = i & 127;
        __half wh = __float2half_rn(Wmsg[k * 128 + n]);
        uint32_t off = toffW(n, k >> 3) + (k & 7) * 2;
        *reinterpret_cast<__half*>(smem + SM_W + off) = wh;
    }
    if (tid < 128) reinterpret_cast<float*>(smem + SM_BIAS)[tid] = bmsg[tid];
    __syncthreads();

    // ---- gather constants: warp handles 8 rows, 4 threads/row ----
    const int g_r   = lane & 7;            // row within warp's 8
    const int g_row = (wid << 3) + g_r;    // tile row 0..63
    const int g_t   = lane >> 3;           // 0..3: (sel, h)
    const int g_sel = g_t & 1;             // 0 = node feats, 1 = edge feats
    const int g_h   = g_t >> 1;            // 0 = hi, 1 = lo

    // ---- warp tiling for MMA: 2(m) x 4(n), warp tile m32 x n32, K=256 ----
    const int mbase = (wid & 1) * 32;
    const int nbase = (wid >> 1) * 32;
    const int mrel  = lane & 15;
    const int khA   = lane >> 4;
    const int nrel  = (lane & 7) + ((lane >> 4) << 3);
    const int khB   = (lane >> 3) & 1;
    const uint32_t swzA = (uint32_t)(mrel & 7);
    const uint32_t swzB = (uint32_t)(nrel & 7);
    uint32_t aRow[2], bRow[2];
    #pragma unroll
    for (int mt = 0; mt < 2; ++mt) aRow[mt] = (uint32_t)(mbase + mt * 16 + mrel) << 9;
    #pragma unroll
    for (int g = 0; g < 2; ++g) bRow[g] = (uint32_t)(nbase + g * 16 + nrel) << 8;

    // bias pairs: c = nbase + nt*8 + (lane&3)*2
    float bx[4], by[4];
    {
        const float* bsm = reinterpret_cast<const float*>(smem + SM_BIAS);
        #pragma unroll
        for (int nt = 0; nt < 4; ++nt) {
            float2 bb = *reinterpret_cast<const float2*>(bsm + nbase + nt * 8 + (lane & 3) * 2);
            bx[nt] = bb.x; by[nt] = bb.y;
        }
    }

    float acc[2][4][4];
    #pragma unroll
    for (int mt = 0; mt < 2; ++mt)
        #pragma unroll
        for (int nt = 0; nt < 4; ++nt)
            #pragma unroll
            for (int q = 0; q < 4; ++q) acc[mt][nt][q] = 0.f;

    const uint32_t xS = sb + SM_X, wS = sb + SM_W;

    const int tiles = (E + 63) >> 6;
    const int grid  = gridDim.x;

    // ---- gather one 64-edge tile (convergent); 8 cpa16/thread ----
    auto issue_tile = [&](int base) {
        int sv = 0;
        {
            int ee = base + (wid << 3) + (lane & 7);
            if (lane < 8 && ee < E) sv = src[ee];
        }
        const int s  = __shfl_sync(0xffffffffu, sv, g_r);   // all lanes participate
        const int eg = base + g_row;
        const bool valid = (eg < E);
        const unsigned char* srow = (g_sel
            ? (g_econv + (size_t)eg * 256)
            : (g_nconv + (size_t)s * 256)) + g_h * 128;
        const int kcb = (g_h << 4) + (g_sel << 3);   // dst kchunk base
        #pragma unroll
        for (int c = 0; c < 8; ++c) {
            const uint32_t d = xS + toffX(g_row, kcb + c);
            if (valid) cpa16(d, srow + c * 16);
            else       sts_zero16(d);
        }
    };

    // ---- pipeline: wait -> sync -> MMA -> sync -> issue(t+1) -> epilogue ----
    int t = blockIdx.x;
    if (t < tiles) issue_tile(t << 6);
    CP_COMMIT();

    for (; t < tiles; t += grid) {
        CP_WAIT0();
        __syncthreads();   // stage visible from all threads

        const int base = t << 6;

        // ---- GEMM: 8 B-loads, each reused for A(kc8) and A(kc8+8) ----
        #pragma unroll
        for (int kc8 = 0; kc8 < 8; ++kc8) {
            const uint32_t kb = (uint32_t)(((kc8 << 1) | khB) ^ swzB) << 4;
            uint32_t bfr[2][4];
            #pragma unroll
            for (int g = 0; g < 2; ++g) ldsm4(bfr[g], wS + bRow[g] + kb);

            #pragma unroll
            for (int half = 0; half < 2; ++half) {
                const int kc = kc8 + half * 8;        // X kchunk pair index 0..15
                const uint32_t ka = (uint32_t)(((kc << 1) | khA) ^ swzA) << 4;
                uint32_t afr[2][4];
                #pragma unroll
                for (int mt = 0; mt < 2; ++mt) ldsm4(afr[mt], xS + aRow[mt] + ka);
                #pragma unroll
                for (int mt = 0; mt < 2; ++mt)
                    #pragma unroll
                    for (int nt = 0; nt < 4; ++nt)
                        mma_f16(acc[mt][nt], afr[mt],
                                bfr[nt >> 1][(nt & 1) * 2], bfr[nt >> 1][(nt & 1) * 2 + 1]);
            }
        }

        __syncthreads();   // all warps finished reading the stage

        const int tn = t + grid;
        if (tn < tiles) issue_tile(tn << 6);
        CP_COMMIT();

        // ---- epilogue: bias+relu, pair-merge via shfl, red.v4 scatter ----
        #pragma unroll
        for (int mt = 0; mt < 2; ++mt) {
            const int rtop = mbase + mt * 16 + (lane >> 2);
            const int etop = base + rtop;
            const int ebot = etop + 8;
            const int dtop = (etop < E) ? dst[etop] : 0;
            const int dbot = (ebot < E) ? dst[ebot] : 0;
            const int cb   = nbase + (lane & 2) * 2;
            #pragma unroll
            for (int nt = 0; nt < 4; ++nt) {
                float v0 = fmaxf(acc[mt][nt][0] + bx[nt], 0.f);
                float v1 = fmaxf(acc[mt][nt][1] + by[nt], 0.f);
                float v2 = fmaxf(acc[mt][nt][2] + bx[nt], 0.f);
                float v3 = fmaxf(acc[mt][nt][3] + by[nt], 0.f);
                float w0 = __shfl_xor_sync(0xffffffffu, v0, 1);
                float w1 = __shfl_xor_sync(0xffffffffu, v1, 1);
                float w2 = __shfl_xor_sync(0xffffffffu, v2, 1);
                float w3 = __shfl_xor_sync(0xffffffffu, v3, 1);
                if (!(lane & 1)) {
                    if (etop < E)
                        red_add_v4(g_hneigh + (size_t)dtop * D_OUT + cb + nt * 8, v0, v1, w0, w1);
                    if (ebot < E)
                        red_add_v4(g_hneigh + (size_t)dbot * D_OUT + cb + nt * 8, v2, v3, w2, w3);
                }
                acc[mt][nt][0] = 0.f; acc[mt][nt][1] = 0.f;
                acc[mt][nt][2] = 0.f; acc[mt][nt][3] = 0.f;
            }
        }
    }
}

// =====================================================================
// Apply kernel (R3): 8 nodes/warp, f32x2 packed along k.
// =====================================================================
#define A_WT 0
#define A_BIAS 24576
#define A_X 24704
#define A_SMEM_FLOATS 37248

__global__ __launch_bounds__(256, 1)
void apply_kernel(const float* __restrict__ nfeats,
                  const float* __restrict__ Wap,
                  const float* __restrict__ bap,
                  float* __restrict__ out,
                  int N)
{
    extern __shared__ float sm[];
    float* wsm  = sm + A_WT;
    float* bsm  = sm + A_BIAS;
    float* xall = sm + A_X;

    for (int half = 0; half < 2; ++half) {
        for (int i = threadIdx.x; i < 3072; i += 256)
            reinterpret_cast<float4*>(xall)[i] =
                reinterpret_cast<const float4*>(Wap + half * 12288)[i];
        __syncthreads();
        for (int i = threadIdx.x; i < 12288; i += 256) {
            int kl = i >> 7, c = i & 127, k = half * 96 + kl;
            wsm[c * 192 + (((k >> 2) ^ ((c >> 2) & 7)) << 2) + (k & 3)] = xall[i];
        }
        __syncthreads();
    }
    if (threadIdx.x < 128) bsm[threadIdx.x] = bap[threadIdx.x];
    __syncthreads();

    const int lane = threadIdx.x & 31;
    const int warp = threadIdx.x >> 5;
    const int gw   = blockIdx.x * 8 + warp;
    const int nw   = gridDim.x * 8;
    const int s7   = lane & 7;

    float* xw = xall + warp * (8 * 196);
    const float* wl = wsm + (lane * 4) * 192;
    const float4 bias4 = *reinterpret_cast<const float4*>(bsm + lane * 4);

    const int h  = lane >> 4;
    const int j  = lane & 15;
    const int cg = j * 12;

    unsigned long long acc[8][4];
    #pragma unroll
    for (int e = 0; e < 8; ++e)
        #pragma unroll
        for (int c = 0; c < 4; ++c) acc[e][c] = 0ull;

    const int tiles = (N + 7) >> 3;
    for (int tile = gw; tile < tiles; tile += nw) {
        const int base = tile * 8;

        #pragma unroll
        for (int r = 0; r < 4; ++r) {
            int nl = r * 2 + h;
            int ng = base + nl;
            if (ng < N) {
                #pragma unroll
                for (int q = 0; q < 3; ++q) {
                    int off = cg + q * 4;
                    float4 v;
                    if (off < D_IN)
                        v = *reinterpret_cast<const float4*>(nfeats + (size_t)ng * D_IN + off);
                    else
                        v = *reinterpret_cast<const float4*>(g_hneigh + (size_t)ng * D_OUT + (off - D_IN));
                    *reinterpret_cast<float4*>(xw + nl * 196 + off) = v;
                }
            }
        }
        __syncwarp();

        #pragma unroll 4
        for (int t = 0; t < 48; ++t) {
            const int wq = ((t ^ s7) << 2);
            ulonglong2 w0 = *reinterpret_cast<const ulonglong2*>(wl + wq);
            ulonglong2 w1 = *reinterpret_cast<const ulonglong2*>(wl + 192 + wq);
            ulonglong2 w2 = *reinterpret_cast<const ulonglong2*>(wl + 384 + wq);
            ulonglong2 w3 = *reinterpret_cast<const ulonglong2*>(wl + 576 + wq);
            #pragma unroll
            for (int e = 0; e < 8; ++e) {
                ulonglong2 xv = *reinterpret_cast<const ulonglong2*>(xw + e * 196 + t * 4);
                ffma2(acc[e][0], xv.x, w0.x); ffma2(acc[e][0], xv.y, w0.y);
                ffma2(acc[e][1], xv.x, w1.x); ffma2(acc[e][1], xv.y, w1.y);
                ffma2(acc[e][2], xv.x, w2.x); ffma2(acc[e][2], xv.y, w2.y);
                ffma2(acc[e][3], xv.x, w3.x); ffma2(acc[e][3], xv.y, w3.y);
            }
        }

        #pragma unroll
        for (int e = 0; e < 8; ++e) {
            int ng = base + e;
            float2 f0 = unpack2(acc[e][0]);
            float2 f1 = unpack2(acc[e][1]);
            float2 f2 = unpack2(acc[e][2]);
            float2 f3 = unpack2(acc[e][3]);
            float4 o;
            o.x = fmaxf(f0.x + f0.y + bias4.x, 0.f);
            o.y = fmaxf(f1.x + f1.y + bias4.y, 0.f);
            o.z = fmaxf(f2.x + f2.y + bias4.z, 0.f);
            o.w = fmaxf(f3.x + f3.y + bias4.w, 0.f);
            if (ng < N)
                *reinterpret_cast<float4*>(out + (size_t)ng * D_OUT + lane * 4) = o;
            acc[e][0] = 0ull; acc[e][1] = 0ull; acc[e][2] = 0ull; acc[e][3] = 0ull;
        }
        __syncwarp();
    }
}

extern "C" void kernel_launch(void* const* d_in, const int* in_sizes, int n_in,
                              void* d_out, int out_size)
{
    const float* nfeats = (const float*)d_in[0];
    const float* efeats = (const float*)d_in[1];
    const float* Wmsg   = (const float*)d_in[2];
    const float* bmsg   = (const float*)d_in[3];
    const float* Wap    = (const float*)d_in[4];
    const float* bap    = (const float*)d_in[5];
    const int*   src    = (const int*)d_in[6];
    const int*   dst    = (const int*)d_in[7];

    const int E = in_sizes[6];
    const int N = in_sizes[0] / D_IN;

    const size_t smem_edge  = SM_EDGE_BYTES;                    // 66048 B (2 CTAs/SM)
    const size_t smem_apply = A_SMEM_FLOATS * sizeof(float);    // 148992 B
    cudaFuncSetAttribute(edge_msg_kernel, cudaFuncAttributeMaxDynamicSharedMemorySize, (int)smem_edge);
    cudaFuncSetAttribute(apply_kernel,    cudaFuncAttributeMaxDynamicSharedMemorySize, (int)smem_apply);

    unsigned char* nconv_p; cudaGetSymbolAddress((void**)&nconv_p, g_nconv);
    unsigned char* econv_p; cudaGetSymbolAddress((void**)&econv_p, g_econv);

    // prepass conversions (fp16 hi/lo)
    {
        int nchunks = N * 16;
        conv_split_kernel<<<(nchunks + 255) / 256, 256>>>(
            (const float4*)nfeats, nconv_p, nchunks);
        int echunks = E * 16;
        conv_split_kernel<<<(echunks + 255) / 256, 256>>>(
            (const float4*)efeats, econv_p, echunks);
    }

    const int n4 = (N * D_OUT) / 4;
    zero_hneigh_kernel<<<(n4 + 255) / 256, 256>>>(n4);
    edge_msg_kernel<<<296, 256, smem_edge>>>(Wmsg, bmsg, src, dst, E);
    apply_kernel<<<152, 256, smem_apply>>>(nfeats, Wap, bap, (float*)d_out, N);
}

// round 13
// speedup vs baseline: 1.5118x; 1.5118x over previous
#include <cuda_runtime.h>
#include <cstdint>

#define D_IN 64
#define D_E 64
#define D_OUT 128
#define MAX_NODES 50000
#define MAX_EDGES 800000

__device__ float g_hneigh[MAX_NODES * D_OUT];
// packed bf16 split rows: per row 128B hi + 128B lo
__device__ __align__(16) unsigned char g_nconv[(size_t)MAX_NODES * 256];
__device__ __align__(16) unsigned char g_econv[(size_t)MAX_EDGES * 256];

// ============================ helpers ============================
__device__ __forceinline__ void red_add_v4(float* p, float a, float b, float c, float d) {
    asm volatile("red.global.add.v4.f32 [%0], {%1, %2, %3, %4};"
                 :: "l"(p), "f"(a), "f"(b), "f"(c), "f"(d) : "memory");
}
__device__ __forceinline__ uint32_t smem_u32(const void* p) {
    uint32_t a;
    asm("{ .reg .u64 t; cvta.to.shared.u64 t, %1; cvt.u32.u64 %0, t; }" : "=r"(a) : "l"(p));
    return a;
}
__device__ __forceinline__ void ldsm4(uint32_t* r, uint32_t addr) {
    asm volatile("ldmatrix.sync.aligned.m8n8.x4.shared.b16 {%0,%1,%2,%3}, [%4];"
                 : "=r"(r[0]), "=r"(r[1]), "=r"(r[2]), "=r"(r[3]) : "r"(addr));
}
__device__ __forceinline__ void mma_bf16(float* c, const uint32_t* a, uint32_t b0, uint32_t b1) {
    asm volatile("mma.sync.aligned.m16n8k16.row.col.f32.bf16.bf16.f32 "
                 "{%0,%1,%2,%3}, {%4,%5,%6,%7}, {%8,%9}, {%0,%1,%2,%3};"
                 : "+f"(c[0]), "+f"(c[1]), "+f"(c[2]), "+f"(c[3])
                 : "r"(a[0]), "r"(a[1]), "r"(a[2]), "r"(a[3]), "r"(b0), "r"(b1));
}
__device__ __forceinline__ void cpa16(uint32_t dst, const void* src) {
    asm volatile("cp.async.cg.shared.global [%0], [%1], 16;" :: "r"(dst), "l"(src));
}
#define CP_COMMIT() asm volatile("cp.async.commit_group;" ::: "memory")
#define CP_WAIT0()  asm volatile("cp.async.wait_group 0;" ::: "memory")
__device__ __forceinline__ void sts_zero16(uint32_t dst) {
    asm volatile("st.shared.v4.b32 [%0], {%1,%1,%1,%1};" :: "r"(dst), "r"(0u));
}

__global__ void zero_hneigh_kernel(int n4) {
    int i = blockIdx.x * blockDim.x + threadIdx.x;
    if (i < n4)
        reinterpret_cast<float4*>(g_hneigh)[i] = make_float4(0.f, 0.f, 0.f, 0.f);
}

// ---------- prepass: fp32 rows -> packed bf16 hi/lo rows (256B/row) ----------
__global__ void conv_split_kernel(const float4* __restrict__ in,
                                  unsigned char* __restrict__ out, int nchunks) {
    int i = blockIdx.x * blockDim.x + threadIdx.x;
    if (i >= nchunks) return;
    int row = i >> 4, q = i & 15;
    float4 v = in[i];
    uint32_t h01, h23;
    asm("cvt.rn.bf16x2.f32 %0, %1, %2;" : "=r"(h01) : "f"(v.y), "f"(v.x));
    asm("cvt.rn.bf16x2.f32 %0, %1, %2;" : "=r"(h23) : "f"(v.w), "f"(v.z));
    float hx = __uint_as_float(h01 << 16);
    float hy = __uint_as_float(h01 & 0xffff0000u);
    float hz = __uint_as_float(h23 << 16);
    float hw = __uint_as_float(h23 & 0xffff0000u);
    uint32_t l01, l23;
    asm("cvt.rn.bf16x2.f32 %0, %1, %2;" : "=r"(l01) : "f"(v.y - hy), "f"(v.x - hx));
    asm("cvt.rn.bf16x2.f32 %0, %1, %2;" : "=r"(l23) : "f"(v.w - hw), "f"(v.z - hz));
    unsigned char* o = out + (size_t)row * 256;
    *reinterpret_cast<uint2*>(o + q * 8)       = make_uint2(h01, h23);
    *reinterpret_cast<uint2*>(o + 128 + q * 8) = make_uint2(l01, l23);
}

// =====================================================================
// Edge kernel (R9 verbatim — best measured): 2 CTAs/SM x 256 thr,
// 64-edge tiles, single-buffer cp.async, bf16 split-2 3-pass mma.
// =====================================================================
#define SM_WHI  0u
#define SM_WLO  32768u
#define SM_XHI  65536u
#define SM_XLO  81920u
#define SM_BIAS 98304u
#define SM_EDGE_BYTES 98816u

__device__ __forceinline__ uint32_t toff(int row, int kchunk) {
    return ((uint32_t)row << 8) + ((uint32_t)(kchunk ^ (row & 7)) << 4);
}

__global__ __launch_bounds__(256, 2)
void edge_msg_kernel(const float* __restrict__ Wmsg,
                     const float* __restrict__ bmsg,
                     const int* __restrict__ src,
                     const int* __restrict__ dst,
                     int E)
{
    extern __shared__ char smem[];
    const uint32_t sb = smem_u32(smem);
    const int tid  = threadIdx.x;
    const int lane = tid & 31;
    const int wid  = tid >> 5;

    for (int i = tid; i < 128 * 128; i += 256) {
        int n = i >> 7, k = i & 127;
        float w = Wmsg[k * 128 + n];
        uint32_t hb;
        asm("cvt.rn.bf16x2.f32 %0, %1, %2;" : "=r"(hb) : "f"(0.f), "f"(w));
        float hf = __uint_as_float(hb << 16);
        uint32_t lb;
        asm("cvt.rn.bf16x2.f32 %0, %1, %2;" : "=r"(lb) : "f"(0.f), "f"(w - hf));
        uint32_t off = toff(n, k >> 3) + (k & 7) * 2;
        *reinterpret_cast<uint16_t*>(smem + SM_WHI + off) = (uint16_t)hb;
        *reinterpret_cast<uint16_t*>(smem + SM_WLO + off) = (uint16_t)lb;
    }
    if (tid < 128) reinterpret_cast<float*>(smem + SM_BIAS)[tid] = bmsg[tid];
    __syncthreads();

    const int g_r    = lane & 7;
    const int g_row  = (wid << 3) + g_r;
    const int g_half = (lane >> 3) & 1;
    const int g_quart = lane >> 4;

    const int mbase = (wid & 1) * 32;
    const int nbase = (wid >> 1) * 32;
    const int mrel  = lane & 15;
    const int khA   = lane >> 4;
    const int nrel  = (lane & 7) + ((lane >> 4) << 3);
    const int khB   = (lane >> 3) & 1;
    const uint32_t swzA = (uint32_t)(mrel & 7);
    const uint32_t swzB = (uint32_t)(nrel & 7);
    uint32_t aRow[2], bRow[2];
    #pragma unroll
    for (int mt = 0; mt < 2; ++mt) aRow[mt] = (uint32_t)(mbase + mt * 16 + mrel) << 8;
    #pragma unroll
    for (int g = 0; g < 2; ++g) bRow[g] = (uint32_t)(nbase + g * 16 + nrel) << 8;

    float bx[4], by[4];
    {
        const float* bsm = reinterpret_cast<const float*>(smem + SM_BIAS);
        #pragma unroll
        for (int nt = 0; nt < 4; ++nt) {
            float2 bb = *reinterpret_cast<const float2*>(bsm + nbase + nt * 8 + (lane & 3) * 2);
            bx[nt] = bb.x; by[nt] = bb.y;
        }
    }

    float acc[2][4][4];
    #pragma unroll
    for (int mt = 0; mt < 2; ++mt)
        #pragma unroll
        for (int nt = 0; nt < 4; ++nt)
            #pragma unroll
            for (int q = 0; q < 4; ++q) acc[mt][nt][q] = 0.f;

    const uint32_t xhi = sb + SM_XHI, xlo = sb + SM_XLO;
    const uint32_t wHi = sb + SM_WHI, wLo = sb + SM_WLO;

    const int tiles = (E + 63) >> 6;
    const int grid  = gridDim.x;

    auto issue_tile = [&](int base) {
        int sv = 0;
        {
            int ee = base + (wid << 3) + (lane & 7);
            if (lane < 8 && ee < E) sv = src[ee];
        }
        const int s  = __shfl_sync(0xffffffffu, sv, g_r);
        const int eg = base + g_row;
        const bool valid = (eg < E);
        const unsigned char* srow = (g_half == 0)
            ? (g_nconv + (size_t)s * 256)
            : (g_econv + (size_t)eg * 256);
        #pragma unroll
        for (int c = 0; c < 4; ++c) {
            const int cl = (g_quart << 2) + c;
            const int kchunk = (g_half << 3) + cl;
            const uint32_t dhi = xhi + toff(g_row, kchunk);
            const uint32_t dlo = xlo + toff(g_row, kchunk);
            if (valid) {
                cpa16(dhi, srow + cl * 16);
                cpa16(dlo, srow + 128 + cl * 16);
            } else {
                sts_zero16(dhi);
                sts_zero16(dlo);
            }
        }
    };

    int t = blockIdx.x;
    if (t < tiles) issue_tile(t << 6);
    CP_COMMIT();

    for (; t < tiles; t += grid) {
        CP_WAIT0();
        __syncthreads();

        const int base = t << 6;

        #pragma unroll
        for (int kc = 0; kc < 8; ++kc) {
            const uint32_t ka = (uint32_t)(((kc << 1) | khA) ^ swzA) << 4;
            const uint32_t kb = (uint32_t)(((kc << 1) | khB) ^ swzB) << 4;
            uint32_t ahi[2][4], alo[2][4], bfr[2][4];
            #pragma unroll
            for (int mt = 0; mt < 2; ++mt) ldsm4(ahi[mt], xhi + aRow[mt] + ka);
            #pragma unroll
            for (int mt = 0; mt < 2; ++mt) ldsm4(alo[mt], xlo + aRow[mt] + ka);
            #pragma unroll
            for (int g = 0; g < 2; ++g) ldsm4(bfr[g], wHi + bRow[g] + kb);
            #pragma unroll
            for (int mt = 0; mt < 2; ++mt)
                #pragma unroll
                for (int nt = 0; nt < 4; ++nt)
                    mma_bf16(acc[mt][nt], ahi[mt],
                             bfr[nt >> 1][(nt & 1) * 2], bfr[nt >> 1][(nt & 1) * 2 + 1]);
            #pragma unroll
            for (int mt = 0; mt < 2; ++mt)
                #pragma unroll
                for (int nt = 0; nt < 4; ++nt)
                    mma_bf16(acc[mt][nt], alo[mt],
                             bfr[nt >> 1][(nt & 1) * 2], bfr[nt >> 1][(nt & 1) * 2 + 1]);
            #pragma unroll
            for (int g = 0; g < 2; ++g) ldsm4(bfr[g], wLo + bRow[g] + kb);
            #pragma unroll
            for (int mt = 0; mt < 2; ++mt)
                #pragma unroll
                for (int nt = 0; nt < 4; ++nt)
                    mma_bf16(acc[mt][nt], ahi[mt],
                             bfr[nt >> 1][(nt & 1) * 2], bfr[nt >> 1][(nt & 1) * 2 + 1]);
        }

        __syncthreads();

        const int tn = t + grid;
        if (tn < tiles) issue_tile(tn << 6);
        CP_COMMIT();

        #pragma unroll
        for (int mt = 0; mt < 2; ++mt) {
            const int rtop = mbase + mt * 16 + (lane >> 2);
            const int etop = base + rtop;
            const int ebot = etop + 8;
            const int dtop = (etop < E) ? dst[etop] : 0;
            const int dbot = (ebot < E) ? dst[ebot] : 0;
            const int cb   = nbase + (lane & 2) * 2;
            #pragma unroll
            for (int nt = 0; nt < 4; ++nt) {
                float v0 = fmaxf(acc[mt][nt][0] + bx[nt], 0.f);
                float v1 = fmaxf(acc[mt][nt][1] + by[nt], 0.f);
                float v2 = fmaxf(acc[mt][nt][2] + bx[nt], 0.f);
                float v3 = fmaxf(acc[mt][nt][3] + by[nt], 0.f);
                float w0 = __shfl_xor_sync(0xffffffffu, v0, 1);
                float w1 = __shfl_xor_sync(0xffffffffu, v1, 1);
                float w2 = __shfl_xor_sync(0xffffffffu, v2, 1);
                float w3 = __shfl_xor_sync(0xffffffffu, v3, 1);
                if (!(lane & 1)) {
                    if (etop < E)
                        red_add_v4(g_hneigh + (size_t)dtop * D_OUT + cb + nt * 8, v0, v1, w0, w1);
                    if (ebot < E)
                        red_add_v4(g_hneigh + (size_t)dbot * D_OUT + cb + nt * 8, v2, v3, w2, w3);
                }
                acc[mt][nt][0] = 0.f; acc[mt][nt][1] = 0.f;
                acc[mt][nt][2] = 0.f; acc[mt][nt][3] = 0.f;
            }
        }
    }
}

// =====================================================================
// Apply kernel v2 (NEW): tensor-core bf16 split-2 3-pass GEMM.
// Tile = 64 nodes x 128 cols, K = 192 = [nfeats(64) | h_neigh(128)].
// Same warp layout / inner loop shape as the edge kernel; dense loads,
// in-kernel bf16 hi/lo conversion, plain float4 stores.
// =====================================================================
#define AP_WHI  0u
#define AP_WLO  49152u
#define AP_XHI  98304u
#define AP_XLO  122880u
#define AP_BIAS 147456u
#define AP_SMEM_BYTES 147968u

// 384B rows (K=192 bf16), 16B-chunk XOR swizzle (chunks 0..23)
__device__ __forceinline__ uint32_t toffA(int row, int kchunk) {
    return (uint32_t)row * 384u + ((uint32_t)(kchunk ^ (row & 7)) << 4);
}

__global__ __launch_bounds__(256, 1)
void apply_mma_kernel(const float* __restrict__ nfeats,
                      const float* __restrict__ Wap,
                      const float* __restrict__ bap,
                      float* __restrict__ out,
                      int N)
{
    extern __shared__ char smem[];
    const uint32_t sb = smem_u32(smem);
    const int tid  = threadIdx.x;
    const int lane = tid & 31;
    const int wid  = tid >> 5;

    // ---- W split: Wt[n][k] = Wap[k][n] (k=0..191), bf16 hi/lo, swizzled ----
    for (int i = tid; i < 128 * 192; i += 256) {
        int n = i / 192, k = i % 192;
        float w = Wap[k * 128 + n];
        uint32_t hb;
        asm("cvt.rn.bf16x2.f32 %0, %1, %2;" : "=r"(hb) : "f"(0.f), "f"(w));
        float hf = __uint_as_float(hb << 16);
        uint32_t lb;
        asm("cvt.rn.bf16x2.f32 %0, %1, %2;" : "=r"(lb) : "f"(0.f), "f"(w - hf));
        uint32_t off = toffA(n, k >> 3) + (k & 7) * 2;
        *reinterpret_cast<uint16_t*>(smem + AP_WHI + off) = (uint16_t)hb;
        *reinterpret_cast<uint16_t*>(smem + AP_WLO + off) = (uint16_t)lb;
    }
    if (tid < 128) reinterpret_cast<float*>(smem + AP_BIAS)[tid] = bap[tid];
    __syncthreads();

    // ---- warp tiling: 2(m) x 4(n), warp tile m32 x n32, K=192 ----
    const int mbase = (wid & 1) * 32;
    const int nbase = (wid >> 1) * 32;
    const int mrel  = lane & 15;
    const int khA   = lane >> 4;
    const int nrel  = (lane & 7) + ((lane >> 4) << 3);
    const int khB   = (lane >> 3) & 1;
    const uint32_t swzA = (uint32_t)(mrel & 7);
    const uint32_t swzB = (uint32_t)(nrel & 7);
    uint32_t aRow[2], bRow[2];
    #pragma unroll
    for (int mt = 0; mt < 2; ++mt) aRow[mt] = (uint32_t)(mbase + mt * 16 + mrel) * 384u;
    #pragma unroll
    for (int g = 0; g < 2; ++g) bRow[g] = (uint32_t)(nbase + g * 16 + nrel) * 384u;

    float bx[4], by[4];
    {
        const float* bsm = reinterpret_cast<const float*>(smem + AP_BIAS);
        #pragma unroll
        for (int nt = 0; nt < 4; ++nt) {
            float2 bb = *reinterpret_cast<const float2*>(bsm + nbase + nt * 8 + (lane & 3) * 2);
            bx[nt] = bb.x; by[nt] = bb.y;
        }
    }

    // ---- fill constants: 4 threads per row, 6 chunks each ----
    const int f_row = tid >> 2;       // 0..63
    const int f_q   = tid & 3;        // chunk group

    const uint32_t xhi = sb + AP_XHI, xlo = sb + AP_XLO;
    const uint32_t wHi = sb + AP_WHI, wLo = sb + AP_WLO;

    float acc[2][4][4];
    #pragma unroll
    for (int mt = 0; mt < 2; ++mt)
        #pragma unroll
        for (int nt = 0; nt < 4; ++nt)
            #pragma unroll
            for (int q = 0; q < 4; ++q) acc[mt][nt][q] = 0.f;

    const int tiles = (N + 63) >> 6;
    for (int t = blockIdx.x; t < tiles; t += gridDim.x) {
        const int base = t << 6;
        const int node = base + f_row;
        const bool valid = (node < N);

        // ---- fill X: convert [nfeats | h_neigh] fp32 -> bf16 hi/lo ----
        #pragma unroll
        for (int cc = 0; cc < 6; ++cc) {
            const int c = f_q * 6 + cc;      // chunk 0..23
            float4 v0, v1;
            if (valid) {
                const int col = c * 8;
                const float* srcp = (c < 8)
                    ? (nfeats + (size_t)node * D_IN + col)
                    : (g_hneigh + (size_t)node * D_OUT + (col - D_IN));
                v0 = reinterpret_cast<const float4*>(srcp)[0];
                v1 = reinterpret_cast<const float4*>(srcp)[1];
            } else {
                v0 = make_float4(0.f, 0.f, 0.f, 0.f); v1 = v0;
            }
            uint32_t h01, h23, h45, h67;
            asm("cvt.rn.bf16x2.f32 %0, %1, %2;" : "=r"(h01) : "f"(v0.y), "f"(v0.x));
            asm("cvt.rn.bf16x2.f32 %0, %1, %2;" : "=r"(h23) : "f"(v0.w), "f"(v0.z));
            asm("cvt.rn.bf16x2.f32 %0, %1, %2;" : "=r"(h45) : "f"(v1.y), "f"(v1.x));
            asm("cvt.rn.bf16x2.f32 %0, %1, %2;" : "=r"(h67) : "f"(v1.w), "f"(v1.z));
            float r0 = v0.x - __uint_as_float(h01 << 16);
            float r1 = v0.y - __uint_as_float(h01 & 0xffff0000u);
            float r2 = v0.z - __uint_as_float(h23 << 16);
            float r3 = v0.w - __uint_as_float(h23 & 0xffff0000u);
            float r4 = v1.x - __uint_as_float(h45 << 16);
            float r5 = v1.y - __uint_as_float(h45 & 0xffff0000u);
            float r6 = v1.z - __uint_as_float(h67 << 16);
            float r7 = v1.w - __uint_as_float(h67 & 0xffff0000u);
            uint32_t l01, l23, l45, l67;
            asm("cvt.rn.bf16x2.f32 %0, %1, %2;" : "=r"(l01) : "f"(r1), "f"(r0));
            asm("cvt.rn.bf16x2.f32 %0, %1, %2;" : "=r"(l23) : "f"(r3), "f"(r2));
            asm("cvt.rn.bf16x2.f32 %0, %1, %2;" : "=r"(l45) : "f"(r5), "f"(r4));
            asm("cvt.rn.bf16x2.f32 %0, %1, %2;" : "=r"(l67) : "f"(r7), "f"(r6));
            const uint32_t offc = toffA(f_row, c);
            asm volatile("st.shared.v4.b32 [%0], {%1,%2,%3,%4};"
                         :: "r"(xhi + offc), "r"(h01), "r"(h23), "r"(h45), "r"(h67));
            asm volatile("st.shared.v4.b32 [%0], {%1,%2,%3,%4};"
                         :: "r"(xlo + offc), "r"(l01), "r"(l23), "r"(l45), "r"(l67));
        }
        __syncthreads();

        // ---- MMA: Xhi*Whi + Xlo*Whi + Xhi*Wlo, K=192 (12 k16-chunks) ----
        #pragma unroll
        for (int kc = 0; kc < 12; ++kc) {
            const uint32_t ka = (uint32_t)(((kc << 1) | khA) ^ swzA) << 4;
            const uint32_t kb = (uint32_t)(((kc << 1) | khB) ^ swzB) << 4;
            uint32_t ahi[2][4], alo[2][4], bfr[2][4];
            #pragma unroll
            for (int mt = 0; mt < 2; ++mt) ldsm4(ahi[mt], xhi + aRow[mt] + ka);
            #pragma unroll
            for (int mt = 0; mt < 2; ++mt) ldsm4(alo[mt], xlo + aRow[mt] + ka);
            #pragma unroll
            for (int g = 0; g < 2; ++g) ldsm4(bfr[g], wHi + bRow[g] + kb);
            #pragma unroll
            for (int mt = 0; mt < 2; ++mt)
                #pragma unroll
                for (int nt = 0; nt < 4; ++nt)
                    mma_bf16(acc[mt][nt], ahi[mt],
                             bfr[nt >> 1][(nt & 1) * 2], bfr[nt >> 1][(nt & 1) * 2 + 1]);
            #pragma unroll
            for (int mt = 0; mt < 2; ++mt)
                #pragma unroll
                for (int nt = 0; nt < 4; ++nt)
                    mma_bf16(acc[mt][nt], alo[mt],
                             bfr[nt >> 1][(nt & 1) * 2], bfr[nt >> 1][(nt & 1) * 2 + 1]);
            #pragma unroll
            for (int g = 0; g < 2; ++g) ldsm4(bfr[g], wLo + bRow[g] + kb);
            #pragma unroll
            for (int mt = 0; mt < 2; ++mt)
                #pragma unroll
                for (int nt = 0; nt < 4; ++nt)
                    mma_bf16(acc[mt][nt], ahi[mt],
                             bfr[nt >> 1][(nt & 1) * 2], bfr[nt >> 1][(nt & 1) * 2 + 1]);
        }
        __syncthreads();   // X reads done before next tile's fill

        // ---- epilogue: bias+relu, pair-merge via shfl, float4 store ----
        #pragma unroll
        for (int mt = 0; mt < 2; ++mt) {
            const int rtop = mbase + mt * 16 + (lane >> 2);
            const int ntop = base + rtop;
            const int nbot = ntop + 8;
            const int cb   = nbase + (lane & 2) * 2;
            #pragma unroll
            for (int nt = 0; nt < 4; ++nt) {
                float v0 = fmaxf(acc[mt][nt][0] + bx[nt], 0.f);
                float v1 = fmaxf(acc[mt][nt][1] + by[nt], 0.f);
                float v2 = fmaxf(acc[mt][nt][2] + bx[nt], 0.f);
                float v3 = fmaxf(acc[mt][nt][3] + by[nt], 0.f);
                float w0 = __shfl_xor_sync(0xffffffffu, v0, 1);
                float w1 = __shfl_xor_sync(0xffffffffu, v1, 1);
                float w2 = __shfl_xor_sync(0xffffffffu, v2, 1);
                float w3 = __shfl_xor_sync(0xffffffffu, v3, 1);
                if (!(lane & 1)) {
                    if (ntop < N)
                        *reinterpret_cast<float4*>(out + (size_t)ntop * D_OUT + cb + nt * 8)
                            = make_float4(v0, v1, w0, w1);
                    if (nbot < N)
                        *reinterpret_cast<float4*>(out + (size_t)nbot * D_OUT + cb + nt * 8)
                            = make_float4(v2, v3, w2, w3);
                }
                acc[mt][nt][0] = 0.f; acc[mt][nt][1] = 0.f;
                acc[mt][nt][2] = 0.f; acc[mt][nt][3] = 0.f;
            }
        }
    }
}

extern "C" void kernel_launch(void* const* d_in, const int* in_sizes, int n_in,
                              void* d_out, int out_size)
{
    const float* nfeats = (const float*)d_in[0];
    const float* efeats = (const float*)d_in[1];
    const float* Wmsg   = (const float*)d_in[2];
    const float* bmsg   = (const float*)d_in[3];
    const float* Wap    = (const float*)d_in[4];
    const float* bap    = (const float*)d_in[5];
    const int*   src    = (const int*)d_in[6];
    const int*   dst    = (const int*)d_in[7];

    const int E = in_sizes[6];
    const int N = in_sizes[0] / D_IN;

    cudaFuncSetAttribute(edge_msg_kernel,  cudaFuncAttributeMaxDynamicSharedMemorySize, (int)SM_EDGE_BYTES);
    cudaFuncSetAttribute(apply_mma_kernel, cudaFuncAttributeMaxDynamicSharedMemorySize, (int)AP_SMEM_BYTES);

    unsigned char* nconv_p; cudaGetSymbolAddress((void**)&nconv_p, g_nconv);
    unsigned char* econv_p; cudaGetSymbolAddress((void**)&econv_p, g_econv);

    // prepass conversions (bf16 hi/lo)
    {
        int nchunks = N * 16;
        conv_split_kernel<<<(nchunks + 255) / 256, 256>>>(
            (const float4*)nfeats, nconv_p, nchunks);
        int echunks = E * 16;
        conv_split_kernel<<<(echunks + 255) / 256, 256>>>(
            (const float4*)efeats, econv_p, echunks);
    }

    const int n4 = (N * D_OUT) / 4;
    zero_hneigh_kernel<<<(n4 + 255) / 256, 256>>>(n4);
    edge_msg_kernel<<<296, 256, SM_EDGE_BYTES>>>(Wmsg, bmsg, src, dst, E);
    apply_mma_kernel<<<148, 256, AP_SMEM_BYTES>>>(nfeats, Wap, bap, (float*)d_out, N);
}

// round 14
// speedup vs baseline: 1.6833x; 1.1135x over previous
#include <cuda_runtime.h>
#include <cstdint>

#define D_IN 64
#define D_E 64
#define D_OUT 128
#define MAX_NODES 50000

__device__ float g_hneigh[MAX_NODES * D_OUT];
// packed bf16 split rows for nfeats: per row 128B hi + 128B lo
__device__ __align__(16) unsigned char g_nconv[(size_t)MAX_NODES * 256];

// ============================ helpers ============================
__device__ __forceinline__ void red_add_v4(float* p, float a, float b, float c, float d) {
    asm volatile("red.global.add.v4.f32 [%0], {%1, %2, %3, %4};"
                 :: "l"(p), "f"(a), "f"(b), "f"(c), "f"(d) : "memory");
}
__device__ __forceinline__ uint32_t smem_u32(const void* p) {
    uint32_t a;
    asm("{ .reg .u64 t; cvta.to.shared.u64 t, %1; cvt.u32.u64 %0, t; }" : "=r"(a) : "l"(p));
    return a;
}
__device__ __forceinline__ void ldsm4(uint32_t* r, uint32_t addr) {
    asm volatile("ldmatrix.sync.aligned.m8n8.x4.shared.b16 {%0,%1,%2,%3}, [%4];"
                 : "=r"(r[0]), "=r"(r[1]), "=r"(r[2]), "=r"(r[3]) : "r"(addr));
}
__device__ __forceinline__ void mma_bf16(float* c, const uint32_t* a, uint32_t b0, uint32_t b1) {
    asm volatile("mma.sync.aligned.m16n8k16.row.col.f32.bf16.bf16.f32 "
                 "{%0,%1,%2,%3}, {%4,%5,%6,%7}, {%8,%9}, {%0,%1,%2,%3};"
                 : "+f"(c[0]), "+f"(c[1]), "+f"(c[2]), "+f"(c[3])
                 : "r"(a[0]), "r"(a[1]), "r"(a[2]), "r"(a[3]), "r"(b0), "r"(b1));
}
__device__ __forceinline__ void cpa16(uint32_t dst, const void* src) {
    asm volatile("cp.async.cg.shared.global [%0], [%1], 16;" :: "r"(dst), "l"(src));
}
#define CP_COMMIT() asm volatile("cp.async.commit_group;" ::: "memory")
#define CP_WAIT0()  asm volatile("cp.async.wait_group 0;" ::: "memory")
__device__ __forceinline__ void sts_zero16(uint32_t dst) {
    asm volatile("st.shared.v4.b32 [%0], {%1,%1,%1,%1};" :: "r"(dst), "r"(0u));
}
// convert 8 fp32 -> 4 bf16x2 hi + 4 bf16x2 lo
__device__ __forceinline__ void split8(float4 v0, float4 v1, uint32_t* h, uint32_t* l) {
    asm("cvt.rn.bf16x2.f32 %0, %1, %2;" : "=r"(h[0]) : "f"(v0.y), "f"(v0.x));
    asm("cvt.rn.bf16x2.f32 %0, %1, %2;" : "=r"(h[1]) : "f"(v0.w), "f"(v0.z));
    asm("cvt.rn.bf16x2.f32 %0, %1, %2;" : "=r"(h[2]) : "f"(v1.y), "f"(v1.x));
    asm("cvt.rn.bf16x2.f32 %0, %1, %2;" : "=r"(h[3]) : "f"(v1.w), "f"(v1.z));
    float r0 = v0.x - __uint_as_float(h[0] << 16);
    float r1 = v0.y - __uint_as_float(h[0] & 0xffff0000u);
    float r2 = v0.z - __uint_as_float(h[1] << 16);
    float r3 = v0.w - __uint_as_float(h[1] & 0xffff0000u);
    float r4 = v1.x - __uint_as_float(h[2] << 16);
    float r5 = v1.y - __uint_as_float(h[2] & 0xffff0000u);
    float r6 = v1.z - __uint_as_float(h[3] << 16);
    float r7 = v1.w - __uint_as_float(h[3] & 0xffff0000u);
    asm("cvt.rn.bf16x2.f32 %0, %1, %2;" : "=r"(l[0]) : "f"(r1), "f"(r0));
    asm("cvt.rn.bf16x2.f32 %0, %1, %2;" : "=r"(l[1]) : "f"(r3), "f"(r2));
    asm("cvt.rn.bf16x2.f32 %0, %1, %2;" : "=r"(l[2]) : "f"(r5), "f"(r4));
    asm("cvt.rn.bf16x2.f32 %0, %1, %2;" : "=r"(l[3]) : "f"(r7), "f"(r6));
}
#define STS128(addr, r) \
    asm volatile("st.shared.v4.b32 [%0], {%1,%2,%3,%4};" \
                 :: "r"(addr), "r"((r)[0]), "r"((r)[1]), "r"((r)[2]), "r"((r)[3]))

__global__ void zero_hneigh_kernel(int n4) {
    int i = blockIdx.x * blockDim.x + threadIdx.x;
    if (i < n4)
        reinterpret_cast<float4*>(g_hneigh)[i] = make_float4(0.f, 0.f, 0.f, 0.f);
}

// ---------- prepass: nfeats fp32 -> packed bf16 hi/lo rows (256B/row) ----------
__global__ void conv_split_kernel(const float4* __restrict__ in,
                                  unsigned char* __restrict__ out, int nchunks) {
    int i = blockIdx.x * blockDim.x + threadIdx.x;
    if (i >= nchunks) return;
    int row = i >> 4, q = i & 15;
    float4 v = in[i];
    uint32_t h01, h23;
    asm("cvt.rn.bf16x2.f32 %0, %1, %2;" : "=r"(h01) : "f"(v.y), "f"(v.x));
    asm("cvt.rn.bf16x2.f32 %0, %1, %2;" : "=r"(h23) : "f"(v.w), "f"(v.z));
    float hx = __uint_as_float(h01 << 16);
    float hy = __uint_as_float(h01 & 0xffff0000u);
    float hz = __uint_as_float(h23 << 16);
    float hw = __uint_as_float(h23 & 0xffff0000u);
    uint32_t l01, l23;
    asm("cvt.rn.bf16x2.f32 %0, %1, %2;" : "=r"(l01) : "f"(v.y - hy), "f"(v.x - hx));
    asm("cvt.rn.bf16x2.f32 %0, %1, %2;" : "=r"(l23) : "f"(v.w - hw), "f"(v.z - hz));
    unsigned char* o = out + (size_t)row * 256;
    *reinterpret_cast<uint2*>(o + q * 8)       = make_uint2(h01, h23);
    *reinterpret_cast<uint2*>(o + 128 + q * 8) = make_uint2(l01, l23);
}

// =====================================================================
// Edge kernel v11: R9 pipeline + in-kernel efeats conversion
// (no econv prepass). 2 CTAs/SM x 256 thr, 64-edge tiles.
// smem: Whi 32K | Wlo 32K | Xhi 16K | Xlo 16K | EST(fp32 efeats) 16K = 112KB
// =====================================================================
#define SM_WHI  0u
#define SM_WLO  32768u
#define SM_XHI  65536u
#define SM_XLO  81920u
#define SM_EST  98304u
#define SM_EDGE_BYTES 114688u

__device__ __forceinline__ uint32_t toff(int row, int kchunk) {
    return ((uint32_t)row << 8) + ((uint32_t)(kchunk ^ (row & 7)) << 4);
}

__global__ __launch_bounds__(256, 2)
void edge_msg_kernel(const float* __restrict__ efeats,
                     const float* __restrict__ Wmsg,
                     const float* __restrict__ bmsg,
                     const int* __restrict__ src,
                     const int* __restrict__ dst,
                     int E)
{
    extern __shared__ char smem[];
    const uint32_t sb = smem_u32(smem);
    const int tid  = threadIdx.x;
    const int lane = tid & 31;
    const int wid  = tid >> 5;

    // ---- W split to smem: Wt[n][k] = Wmsg[k][n], hi/lo bf16, swizzled ----
    for (int i = tid; i < 128 * 128; i += 256) {
        int n = i >> 7, k = i & 127;
        float w = Wmsg[k * 128 + n];
        uint32_t hb;
        asm("cvt.rn.bf16x2.f32 %0, %1, %2;" : "=r"(hb) : "f"(0.f), "f"(w));
        float hf = __uint_as_float(hb << 16);
        uint32_t lb;
        asm("cvt.rn.bf16x2.f32 %0, %1, %2;" : "=r"(lb) : "f"(0.f), "f"(w - hf));
        uint32_t off = toff(n, k >> 3) + (k & 7) * 2;
        *reinterpret_cast<uint16_t*>(smem + SM_WHI + off) = (uint16_t)hb;
        *reinterpret_cast<uint16_t*>(smem + SM_WLO + off) = (uint16_t)lb;
    }
    __syncthreads();

    const int g_r    = lane & 7;
    const int g_row  = (wid << 3) + g_r;
    const int g_half = (lane >> 3) & 1;
    const int g_quart = lane >> 4;

    const int mbase = (wid & 1) * 32;
    const int nbase = (wid >> 1) * 32;
    const int mrel  = lane & 15;
    const int khA   = lane >> 4;
    const int nrel  = (lane & 7) + ((lane >> 4) << 3);
    const int khB   = (lane >> 3) & 1;
    const uint32_t swzA = (uint32_t)(mrel & 7);
    const uint32_t swzB = (uint32_t)(nrel & 7);
    uint32_t aRow[2], bRow[2];
    #pragma unroll
    for (int mt = 0; mt < 2; ++mt) aRow[mt] = (uint32_t)(mbase + mt * 16 + mrel) << 8;
    #pragma unroll
    for (int g = 0; g < 2; ++g) bRow[g] = (uint32_t)(nbase + g * 16 + nrel) << 8;

    // bias pairs from GLOBAL (smem slot removed to fit 112KB)
    float bx[4], by[4];
    #pragma unroll
    for (int nt = 0; nt < 4; ++nt) {
        float2 bb = *reinterpret_cast<const float2*>(bmsg + nbase + nt * 8 + (lane & 3) * 2);
        bx[nt] = bb.x; by[nt] = bb.y;
    }

    float acc[2][4][4];
    #pragma unroll
    for (int mt = 0; mt < 2; ++mt)
        #pragma unroll
        for (int nt = 0; nt < 4; ++nt)
            #pragma unroll
            for (int q = 0; q < 4; ++q) acc[mt][nt][q] = 0.f;

    const uint32_t xhi = sb + SM_XHI, xlo = sb + SM_XLO;
    const uint32_t wHi = sb + SM_WHI, wLo = sb + SM_WLO;
    const uint32_t est = sb + SM_EST;

    // conversion constants (loop-invariant)
    const int cv_row = tid >> 2;       // 0..63
    const int cv_seg = tid & 3;        // 16 floats each
    const int cv_idx = cv_row * 16 + cv_seg * 4;   // float4 index into EST
    const uint32_t cv_hi0 = xhi + toff(cv_row, 8 + 2 * cv_seg);
    const uint32_t cv_hi1 = xhi + toff(cv_row, 9 + 2 * cv_seg);
    const uint32_t cv_lo0 = xlo + toff(cv_row, 8 + 2 * cv_seg);
    const uint32_t cv_lo1 = xlo + toff(cv_row, 9 + 2 * cv_seg);

    const int tiles = (E + 63) >> 6;
    const int grid  = gridDim.x;

    // ---- gather one 64-edge tile: nconv -> X (kchunks 0..7), efeats fp32 -> EST ----
    auto issue_tile = [&](int base) {
        int sv = 0;
        {
            int ee = base + (wid << 3) + (lane & 7);
            if (lane < 8 && ee < E) sv = src[ee];
        }
        const int s  = __shfl_sync(0xffffffffu, sv, g_r);   // all lanes participate
        const int eg = base + g_row;
        const bool valid = (eg < E);
        if (g_half == 0) {
            const unsigned char* srow = g_nconv + (size_t)s * 256;
            #pragma unroll
            for (int c = 0; c < 4; ++c) {
                const int cl = (g_quart << 2) + c;     // 0..7
                const uint32_t dhi = xhi + toff(g_row, cl);
                const uint32_t dlo = xlo + toff(g_row, cl);
                if (valid) {
                    cpa16(dhi, srow + cl * 16);
                    cpa16(dlo, srow + 128 + cl * 16);
                } else {
                    sts_zero16(dhi);
                    sts_zero16(dlo);
                }
            }
        } else {
            const char* erow = reinterpret_cast<const char*>(efeats + (size_t)eg * D_E)
                             + g_quart * 128;
            const uint32_t eb = est + ((uint32_t)g_row << 8) + ((uint32_t)g_quart << 7);
            #pragma unroll
            for (int c = 0; c < 8; ++c) {
                if (valid) cpa16(eb + c * 16, erow + c * 16);
                else       sts_zero16(eb + c * 16);
            }
        }
    };

    int t = blockIdx.x;
    if (t < tiles) issue_tile(t << 6);
    CP_COMMIT();

    for (; t < tiles; t += grid) {
        CP_WAIT0();
        __syncthreads();   // X node-half + EST ready

        // ---- convert EST fp32 -> X hi/lo edge half (kchunks 8..15) ----
        {
            const float4* estp = reinterpret_cast<const float4*>(smem + SM_EST);
            float4 v0 = estp[cv_idx], v1 = estp[cv_idx + 1];
            float4 v2 = estp[cv_idx + 2], v3 = estp[cv_idx + 3];
            uint32_t h[4], l[4];
            split8(v0, v1, h, l);
            STS128(cv_hi0, h);
            STS128(cv_lo0, l);
            split8(v2, v3, h, l);
            STS128(cv_hi1, h);
            STS128(cv_lo1, l);
        }
        __syncthreads();   // X complete

        const int base = t << 6;

        // ---- MMA: Xhi*Whi + Xlo*Whi + Xhi*Wlo ----
        #pragma unroll
        for (int kc = 0; kc < 8; ++kc) {
            const uint32_t ka = (uint32_t)(((kc << 1) | khA) ^ swzA) << 4;
            const uint32_t kb = (uint32_t)(((kc << 1) | khB) ^ swzB) << 4;
            uint32_t ahi[2][4], alo[2][4], bfr[2][4];
            #pragma unroll
            for (int mt = 0; mt < 2; ++mt) ldsm4(ahi[mt], xhi + aRow[mt] + ka);
            #pragma unroll
            for (int mt = 0; mt < 2; ++mt) ldsm4(alo[mt], xlo + aRow[mt] + ka);
            #pragma unroll
            for (int g = 0; g < 2; ++g) ldsm4(bfr[g], wHi + bRow[g] + kb);
            #pragma unroll
            for (int mt = 0; mt < 2; ++mt)
                #pragma unroll
                for (int nt = 0; nt < 4; ++nt)
                    mma_bf16(acc[mt][nt], ahi[mt],
                             bfr[nt >> 1][(nt & 1) * 2], bfr[nt >> 1][(nt & 1) * 2 + 1]);
            #pragma unroll
            for (int mt = 0; mt < 2; ++mt)
                #pragma unroll
                for (int nt = 0; nt < 4; ++nt)
                    mma_bf16(acc[mt][nt], alo[mt],
                             bfr[nt >> 1][(nt & 1) * 2], bfr[nt >> 1][(nt & 1) * 2 + 1]);
            #pragma unroll
            for (int g = 0; g < 2; ++g) ldsm4(bfr[g], wLo + bRow[g] + kb);
            #pragma unroll
            for (int mt = 0; mt < 2; ++mt)
                #pragma unroll
                for (int nt = 0; nt < 4; ++nt)
                    mma_bf16(acc[mt][nt], ahi[mt],
                             bfr[nt >> 1][(nt & 1) * 2], bfr[nt >> 1][(nt & 1) * 2 + 1]);
        }

        __syncthreads();   // all warps done reading X/EST

        const int tn = t + grid;
        if (tn < tiles) issue_tile(tn << 6);
        CP_COMMIT();

        // ---- epilogue: bias+relu, pair-merge via shfl, red.v4 scatter ----
        #pragma unroll
        for (int mt = 0; mt < 2; ++mt) {
            const int rtop = mbase + mt * 16 + (lane >> 2);
            const int etop = base + rtop;
            const int ebot = etop + 8;
            const int dtop = (etop < E) ? dst[etop] : 0;
            const int dbot = (ebot < E) ? dst[ebot] : 0;
            const int cb   = nbase + (lane & 2) * 2;
            #pragma unroll
            for (int nt = 0; nt < 4; ++nt) {
                float v0 = fmaxf(acc[mt][nt][0] + bx[nt], 0.f);
                float v1 = fmaxf(acc[mt][nt][1] + by[nt], 0.f);
                float v2 = fmaxf(acc[mt][nt][2] + bx[nt], 0.f);
                float v3 = fmaxf(acc[mt][nt][3] + by[nt], 0.f);
                float w0 = __shfl_xor_sync(0xffffffffu, v0, 1);
                float w1 = __shfl_xor_sync(0xffffffffu, v1, 1);
                float w2 = __shfl_xor_sync(0xffffffffu, v2, 1);
                float w3 = __shfl_xor_sync(0xffffffffu, v3, 1);
                if (!(lane & 1)) {
                    if (etop < E)
                        red_add_v4(g_hneigh + (size_t)dtop * D_OUT + cb + nt * 8, v0, v1, w0, w1);
                    if (ebot < E)
                        red_add_v4(g_hneigh + (size_t)dbot * D_OUT + cb + nt * 8, v2, v3, w2, w3);
                }
                acc[mt][nt][0] = 0.f; acc[mt][nt][1] = 0.f;
                acc[mt][nt][2] = 0.f; acc[mt][nt][3] = 0.f;
            }
        }
    }
}

// =====================================================================
// Apply kernel (R13, unchanged): tensor-core bf16 split-2 3-pass GEMM.
// =====================================================================
#define AP_WHI  0u
#define AP_WLO  49152u
#define AP_XHI  98304u
#define AP_XLO  122880u
#define AP_BIAS 147456u
#define AP_SMEM_BYTES 147968u

__device__ __forceinline__ uint32_t toffA(int row, int kchunk) {
    return (uint32_t)row * 384u + ((uint32_t)(kchunk ^ (row & 7)) << 4);
}

__global__ __launch_bounds__(256, 1)
void apply_mma_kernel(const float* __restrict__ nfeats,
                      const float* __restrict__ Wap,
                      const float* __restrict__ bap,
                      float* __restrict__ out,
                      int N)
{
    extern __shared__ char smem[];
    const uint32_t sb = smem_u32(smem);
    const int tid  = threadIdx.x;
    const int lane = tid & 31;
    const int wid  = tid >> 5;

    for (int i = tid; i < 128 * 192; i += 256) {
        int n = i / 192, k = i % 192;
        float w = Wap[k * 128 + n];
        uint32_t hb;
        asm("cvt.rn.bf16x2.f32 %0, %1, %2;" : "=r"(hb) : "f"(0.f), "f"(w));
        float hf = __uint_as_float(hb << 16);
        uint32_t lb;
        asm("cvt.rn.bf16x2.f32 %0, %1, %2;" : "=r"(lb) : "f"(0.f), "f"(w - hf));
        uint32_t off = toffA(n, k >> 3) + (k & 7) * 2;
        *reinterpret_cast<uint16_t*>(smem + AP_WHI + off) = (uint16_t)hb;
        *reinterpret_cast<uint16_t*>(smem + AP_WLO + off) = (uint16_t)lb;
    }
    if (tid < 128) reinterpret_cast<float*>(smem + AP_BIAS)[tid] = bap[tid];
    __syncthreads();

    const int mbase = (wid & 1) * 32;
    const int nbase = (wid >> 1) * 32;
    const int mrel  = lane & 15;
    const int khA   = lane >> 4;
    const int nrel  = (lane & 7) + ((lane >> 4) << 3);
    const int khB   = (lane >> 3) & 1;
    const uint32_t swzA = (uint32_t)(mrel & 7);
    const uint32_t swzB = (uint32_t)(nrel & 7);
    uint32_t aRow[2], bRow[2];
    #pragma unroll
    for (int mt = 0; mt < 2; ++mt) aRow[mt] = (uint32_t)(mbase + mt * 16 + mrel) * 384u;
    #pragma unroll
    for (int g = 0; g < 2; ++g) bRow[g] = (uint32_t)(nbase + g * 16 + nrel) * 384u;

    float bx[4], by[4];
    {
        const float* bsm = reinterpret_cast<const float*>(smem + AP_BIAS);
        #pragma unroll
        for (int nt = 0; nt < 4; ++nt) {
            float2 bb = *reinterpret_cast<const float2*>(bsm + nbase + nt * 8 + (lane & 3) * 2);
            bx[nt] = bb.x; by[nt] = bb.y;
        }
    }

    const int f_row = tid >> 2;
    const int f_q   = tid & 3;

    const uint32_t xhi = sb + AP_XHI, xlo = sb + AP_XLO;
    const uint32_t wHi = sb + AP_WHI, wLo = sb + AP_WLO;

    float acc[2][4][4];
    #pragma unroll
    for (int mt = 0; mt < 2; ++mt)
        #pragma unroll
        for (int nt = 0; nt < 4; ++nt)
            #pragma unroll
            for (int q = 0; q < 4; ++q) acc[mt][nt][q] = 0.f;

    const int tiles = (N + 63) >> 6;
    for (int t = blockIdx.x; t < tiles; t += gridDim.x) {
        const int base = t << 6;
        const int node = base + f_row;
        const bool valid = (node < N);

        #pragma unroll
        for (int cc = 0; cc < 6; ++cc) {
            const int c = f_q * 6 + cc;
            float4 v0, v1;
            if (valid) {
                const int col = c * 8;
                const float* srcp = (c < 8)
                    ? (nfeats + (size_t)node * D_IN + col)
                    : (g_hneigh + (size_t)node * D_OUT + (col - D_IN));
                v0 = reinterpret_cast<const float4*>(srcp)[0];
                v1 = reinterpret_cast<const float4*>(srcp)[1];
            } else {
                v0 = make_float4(0.f, 0.f, 0.f, 0.f); v1 = v0;
            }
            uint32_t h[4], l[4];
            split8(v0, v1, h, l);
            const uint32_t offc = toffA(f_row, c);
            STS128(xhi + offc, h);
            STS128(xlo + offc, l);
        }
        __syncthreads();

        #pragma unroll
        for (int kc = 0; kc < 12; ++kc) {
            const uint32_t ka = (uint32_t)(((kc << 1) | khA) ^ swzA) << 4;
            const uint32_t kb = (uint32_t)(((kc << 1) | khB) ^ swzB) << 4;
            uint32_t ahi[2][4], alo[2][4], bfr[2][4];
            #pragma unroll
            for (int mt = 0; mt < 2; ++mt) ldsm4(ahi[mt], xhi + aRow[mt] + ka);
            #pragma unroll
            for (int mt = 0; mt < 2; ++mt) ldsm4(alo[mt], xlo + aRow[mt] + ka);
            #pragma unroll
            for (int g = 0; g < 2; ++g) ldsm4(bfr[g], wHi + bRow[g] + kb);
            #pragma unroll
            for (int mt = 0; mt < 2; ++mt)
                #pragma unroll
                for (int nt = 0; nt < 4; ++nt)
                    mma_bf16(acc[mt][nt], ahi[mt],
                             bfr[nt >> 1][(nt & 1) * 2], bfr[nt >> 1][(nt & 1) * 2 + 1]);
            #pragma unroll
            for (int mt = 0; mt < 2; ++mt)
                #pragma unroll
                for (int nt = 0; nt < 4; ++nt)
                    mma_bf16(acc[mt][nt], alo[mt],
                             bfr[nt >> 1][(nt & 1) * 2], bfr[nt >> 1][(nt & 1) * 2 + 1]);
            #pragma unroll
            for (int g = 0; g < 2; ++g) ldsm4(bfr[g], wLo + bRow[g] + kb);
            #pragma unroll
            for (int mt = 0; mt < 2; ++mt)
                #pragma unroll
                for (int nt = 0; nt < 4; ++nt)
                    mma_bf16(acc[mt][nt], ahi[mt],
                             bfr[nt >> 1][(nt & 1) * 2], bfr[nt >> 1][(nt & 1) * 2 + 1]);
        }
        __syncthreads();

        #pragma unroll
        for (int mt = 0; mt < 2; ++mt) {
            const int rtop = mbase + mt * 16 + (lane >> 2);
            const int ntop = base + rtop;
            const int nbot = ntop + 8;
            const int cb   = nbase + (lane & 2) * 2;
            #pragma unroll
            for (int nt = 0; nt < 4; ++nt) {
                float v0 = fmaxf(acc[mt][nt][0] + bx[nt], 0.f);
                float v1 = fmaxf(acc[mt][nt][1] + by[nt], 0.f);
                float v2 = fmaxf(acc[mt][nt][2] + bx[nt], 0.f);
                float v3 = fmaxf(acc[mt][nt][3] + by[nt], 0.f);
                float w0 = __shfl_xor_sync(0xffffffffu, v0, 1);
                float w1 = __shfl_xor_sync(0xffffffffu, v1, 1);
                float w2 = __shfl_xor_sync(0xffffffffu, v2, 1);
                float w3 = __shfl_xor_sync(0xffffffffu, v3, 1);
                if (!(lane & 1)) {
                    if (ntop < N)
                        *reinterpret_cast<float4*>(out + (size_t)ntop * D_OUT + cb + nt * 8)
                            = make_float4(v0, v1, w0, w1);
                    if (nbot < N)
                        *reinterpret_cast<float4*>(out + (size_t)nbot * D_OUT + cb + nt * 8)
                            = make_float4(v2, v3, w2, w3);
                }
                acc[mt][nt][0] = 0.f; acc[mt][nt][1] = 0.f;
                acc[mt][nt][2] = 0.f; acc[mt][nt][3] = 0.f;
            }
        }
    }
}

extern "C" void kernel_launch(void* const* d_in, const int* in_sizes, int n_in,
                              void* d_out, int out_size)
{
    const float* nfeats = (const float*)d_in[0];
    const float* efeats = (const float*)d_in[1];
    const float* Wmsg   = (const float*)d_in[2];
    const float* bmsg   = (const float*)d_in[3];
    const float* Wap    = (const float*)d_in[4];
    const float* bap    = (const float*)d_in[5];
    const int*   src    = (const int*)d_in[6];
    const int*   dst    = (const int*)d_in[7];

    const int E = in_sizes[6];
    const int N = in_sizes[0] / D_IN;

    cudaFuncSetAttribute(edge_msg_kernel,  cudaFuncAttributeMaxDynamicSharedMemorySize, (int)SM_EDGE_BYTES);
    cudaFuncSetAttribute(apply_mma_kernel, cudaFuncAttributeMaxDynamicSharedMemorySize, (int)AP_SMEM_BYTES);

    unsigned char* nconv_p; cudaGetSymbolAddress((void**)&nconv_p, g_nconv);

    // prepass: nfeats only (efeats converted in-kernel now)
    {
        int nchunks = N * 16;
        conv_split_kernel<<<(nchunks + 255) / 256, 256>>>(
            (const float4*)nfeats, nconv_p, nchunks);
    }

    const int n4 = (N * D_OUT) / 4;
    zero_hneigh_kernel<<<(n4 + 255) / 256, 256>>>(n4);
    edge_msg_kernel<<<296, 256, SM_EDGE_BYTES>>>(efeats, Wmsg, bmsg, src, dst, E);
    apply_mma_kernel<<<148, 256, AP_SMEM_BYTES>>>(nfeats, Wap, bap, (float*)d_out, N);
}